// round 10
// baseline (speedup 1.0000x reference)
#include <cuda_runtime.h>
#include <cuda_bf16.h>

#define T_DIM 1024
#define F_DIM 128
#define F2    (F_DIM / 2)     // 64 float2 per t-row
#define UNROLL 8
#define EPS_F 1e-5f

typedef unsigned long long u64;

// Packed f32x2 ALU (sm_103a FFMA2 path — PTX-only, ptxas never auto-fuses)
#define ADD2(d, a, b)    asm("add.rn.f32x2 %0, %1, %2;"      : "=l"(d) : "l"(a), "l"(b))
#define MUL2(d, a, b)    asm("mul.rn.f32x2 %0, %1, %2;"      : "=l"(d) : "l"(a), "l"(b))
#define FMA2(d, a, b, c) asm("fma.rn.f32x2 %0, %1, %2, %3;"  : "=l"(d) : "l"(a), "l"(b), "l"(c))
#define PACK2(d, lo, hi) asm("mov.b64 %0, {%1, %2};"         : "=l"(d) : "f"(lo), "f"(hi))
#define UNPK2(lo, hi, s) asm("mov.b64 {%0, %1}, %2;"         : "=f"(lo), "=f"(hi) : "l"(s))

// One block (64 threads = 2 warps) per (b, c) row; thread owns 2 adjacent
// f-channels held PACKED in 64-bit regs. Memory schedule identical to the
// 161.8us/79.2%-DRAM R9 kernel (dist-1 branch-free ping-pong, __ldcs loads,
// WB stores). All element math is f32x2-packed: ~2x fewer math instructions
// per byte -> lower issue power -> higher sustained clock in the replay loop.
__global__ __launch_bounds__(64, 14)
void cumulative_groupnorm_kernel(const u64* __restrict__ x,
                                 const float* __restrict__ weight,
                                 const float* __restrict__ bias,
                                 u64* __restrict__ out,
                                 int C)
{
    __shared__ u64 s_inv2[T_DIM];    // packed (1/(t+1), 1/(t+1)) LUT, LDS.64
    const int tid = threadIdx.x;     // 0..63
    const int bc  = blockIdx.x;

    #pragma unroll
    for (int i = 0; i < T_DIM / 64; i++) {
        int idx = tid + i * 64;
        float inv = 1.0f / (float)(idx + 1);
        u64 p; PACK2(p, inv, inv);
        s_inv2[idx] = p;
    }
    __syncthreads();

    const int c = bc % C;
    const float wf = weight[c];
    const float bf = bias[c];
    u64 w2, bb2, eps2, neg1;
    PACK2(w2,   wf,     wf);
    PACK2(bb2,  bf,     bf);
    PACK2(eps2, EPS_F,  EPS_F);
    PACK2(neg1, -1.0f, -1.0f);

    const size_t base = (size_t)bc * T_DIM * F2 + tid;
    const u64* __restrict__ xp = x + base;
    u64* __restrict__ op = out + base;

    u64 s2 = 0ull, q2 = 0ull;        // packed running sum / sum-of-squares
    u64 vA[UNROLL], vB[UNROLL];

#define LOAD_T(buf, tbase)                                              \
    _Pragma("unroll")                                                   \
    for (int j = 0; j < UNROLL; j++)                                    \
        buf[j] = __ldcs(xp + (size_t)((tbase) + j) * F2);

#define PROC_T(buf, tbase)                                              \
    _Pragma("unroll")                                                   \
    for (int j = 0; j < UNROLL; j++) {                                  \
        const int tt = (tbase) + j;                                     \
        const u64 val = buf[j];                                         \
        ADD2(s2, s2, val);                                              \
        FMA2(q2, val, val, q2);                                         \
        const u64 inv2 = s_inv2[tt];                                    \
        u64 m2, t2, nm2, var2, ve2;                                     \
        MUL2(m2, s2, inv2);           /* mean           */              \
        MUL2(t2, q2, inv2);           /* E[x^2]         */              \
        MUL2(nm2, m2, neg1);          /* -mean          */              \
        FMA2(var2, m2, nm2, t2);      /* E[x^2]-mean^2  */              \
        ADD2(ve2, var2, eps2);                                          \
        float v0, v1; UNPK2(v0, v1, ve2);                               \
        const float r0 = rsqrtf(v0), r1 = rsqrtf(v1);                   \
        u64 r2x; PACK2(r2x, r0, r1);                                    \
        u64 d2, dr2, o2;                                                \
        ADD2(d2, val, nm2);           /* x - mean       */              \
        MUL2(dr2, d2, r2x);                                             \
        FMA2(o2, dr2, w2, bb2);       /* *w + b         */              \
        op[(size_t)tt * F2] = o2;                                       \
    }

    // Prologue: tile 0 in flight.
    LOAD_T(vA, 0)

    // Steady state: branch-free, always two tiles of loads in flight.
    #pragma unroll 1
    for (int t = 0; t < T_DIM - 2 * UNROLL; t += 2 * UNROLL) {
        LOAD_T(vB, t + UNROLL)
        PROC_T(vA, t)
        LOAD_T(vA, t + 2 * UNROLL)
        PROC_T(vB, t + UNROLL)
    }

    // Epilogue: last two tiles.
    LOAD_T(vB, T_DIM - UNROLL)
    PROC_T(vA, T_DIM - 2 * UNROLL)
    PROC_T(vB, T_DIM - UNROLL)

#undef LOAD_T
#undef PROC_T
}

extern "C" void kernel_launch(void* const* d_in, const int* in_sizes, int n_in,
                              void* d_out, int out_size)
{
    const u64* x        = (const u64*)d_in[0];
    const float* weight = (const float*)d_in[1];
    const float* bias   = (const float*)d_in[2];
    u64* out            = (u64*)d_out;

    const int C    = in_sizes[1];                       // 256
    const int n_bc = in_sizes[0] / (T_DIM * F_DIM);     // B*C = 1024

    cumulative_groupnorm_kernel<<<n_bc, 64>>>(x, weight, bias, out, C);
}